// round 17
// baseline (speedup 1.0000x reference)
#include <cuda_runtime.h>
#include <cuda_fp16.h>

// GNNPolicy: 2-layer GCN + node logits head + graph mean-pool value head.
// CSR-gather aggregation with fp16 feature tables (fp32 accumulation),
// smem-staged GEMMs with f32x2 FMA, stream-forked GEMM1 || CSR build,
// gather1+GEMM2 fused, gather2+heads fused. Self-cleaning buffers (no zero
// kernel): every replay ends with g_cnt/g_pooled/g_counts zeroed.
// Inputs: x[N,128] f32, edge_index[2,E] int32, batch[N] int32,
//   W1[128,64], b1[64], W2[64,64], b2[64], Wa[64,1], ba[1], Wc[64,1], bc[1]
// Output: concat(action_logits[N], value[G]) as float32, out_size = N + G.

#define HD 64
#define MAXN 100000
#define MAXE 1600000
#define MAXG 64
#define SCB  1024   // scan block width

typedef unsigned long long u64;

// ---- scratch (zero-initialized at module load; kept zeroed by construction) ----
__device__ __align__(16) int     g_cnt[MAXN];
__device__ __align__(16) int     g_rowptr[MAXN];
__device__ __align__(16) int     g_cursor[MAXN];
__device__ __align__(16) int     g_csrc[MAXE];
__device__ __align__(16) int     g_bsum[256];
__device__ __align__(16) float   g_dinv[MAXN];
__device__ __align__(16) __half2 g_T [(size_t)MAXN * 32];  // layer1: raw X@W1 (fp16)
__device__ __align__(16) __half2 g_T2[(size_t)MAXN * 32];  // layer2: premult dinv (fp16)
__device__ __align__(16) float   g_pooled[MAXG * HD];
__device__ __align__(16) float   g_counts[MAXG];

// ---- packed f32x2 helpers ----
__device__ __forceinline__ u64 pk2(float a, float b) {
    u64 r; asm("mov.b64 %0, {%1, %2};" : "=l"(r) : "f"(a), "f"(b)); return r;
}
__device__ __forceinline__ void fma2(u64& d, u64 a, u64 b) {
    asm("fma.rn.f32x2 %0, %1, %2, %0;" : "+l"(d) : "l"(a), "l"(b));
}
__device__ __forceinline__ float hsum2(u64 v) {
    float x, y; asm("mov.b64 {%0, %1}, %2;" : "=f"(x), "=f"(y) : "l"(v)); return x + y;
}

// load 4 consecutive halves (chunk l of a 64-half row) as float4
__device__ __forceinline__ float4 ldh4(const __half2* row, int l) {
    uint2 q = ((const uint2*)row)[l];
    float2 f0 = __half22float2(*(__half2*)&q.x);
    float2 f1 = __half22float2(*(__half2*)&q.y);
    return make_float4(f0.x, f0.y, f1.x, f1.y);
}

__device__ __forceinline__ void atomic_add_v4(float4* addr, float4 v) {
#if defined(__CUDA_ARCH__) && (__CUDA_ARCH__ >= 900)
    atomicAdd(addr, v);
#else
    float* a = (float*)addr;
    atomicAdd(a + 0, v.x); atomicAdd(a + 1, v.y);
    atomicAdd(a + 2, v.z); atomicAdd(a + 3, v.w);
#endif
}

// ---- histogram over dst (2 edges per thread, int2 loads) ----
__global__ void k_hist(const int* __restrict__ ei, int E, int n) {
    int p = blockIdx.x * blockDim.x + threadIdx.x;
    int e = p * 2;
    if (e + 1 < E) {
        int2 d = *(const int2*)(ei + E + e);
        if ((unsigned)d.x < (unsigned)n) atomicAdd(&g_cnt[d.x], 1);
        if ((unsigned)d.y < (unsigned)n) atomicAdd(&g_cnt[d.y], 1);
    } else if (e < E) {
        int d = ei[E + e];
        if ((unsigned)d < (unsigned)n) atomicAdd(&g_cnt[d], 1);
    }
}

// ---- scan level 1: shuffle-based (2 barriers instead of 20) ----
__global__ void k_scan1(int n) {
    __shared__ int ws[32];
    __shared__ int wsx[32];
    int t = threadIdx.x, lane = t & 31, w = t >> 5;
    int i = blockIdx.x * SCB + t;
    int v = (i < n) ? g_cnt[i] : 0;
    int s = v;
#pragma unroll
    for (int o = 1; o < 32; o <<= 1) {
        int x = __shfl_up_sync(0xffffffffu, s, o);
        if (lane >= o) s += x;
    }
    if (lane == 31) ws[w] = s;
    __syncthreads();
    if (w == 0) {
        int u = ws[lane];
        int p = u;
#pragma unroll
        for (int o = 1; o < 32; o <<= 1) {
            int x = __shfl_up_sync(0xffffffffu, p, o);
            if (lane >= o) p += x;
        }
        wsx[lane] = p - u;
        if (lane == 31) g_bsum[blockIdx.x] = p;
    }
    __syncthreads();
    if (i < n) g_rowptr[i] = s - v + wsx[w];
}

// ---- scanB: shuffle scan of block sums (<=256) + apply + cursors + dinv ----
__global__ void k_scanB(int n, int nb) {
    __shared__ int ws[8];
    __shared__ int off[256];
    int t = threadIdx.x, lane = t & 31, w = t >> 5;
    int v = (t < nb) ? g_bsum[t] : 0;
    int s = v;
#pragma unroll
    for (int o = 1; o < 32; o <<= 1) {
        int x = __shfl_up_sync(0xffffffffu, s, o);
        if (lane >= o) s += x;
    }
    if (lane == 31) ws[w] = s;
    __syncthreads();
    int base = 0;
#pragma unroll
    for (int k = 0; k < 8; k++) base += (k < w) ? ws[k] : 0;
    off[t] = s - v + base;       // exclusive scan of g_bsum
    __syncthreads();
    int i = blockIdx.x * 256 + t;
    if (i < n) {
        int rp = g_rowptr[i] + off[i >> 10];
        g_rowptr[i] = rp;
        g_cursor[i] = rp;
        g_dinv[i]   = rsqrtf((float)(g_cnt[i] + 1));
    }
}

// ---- fill CSR (2 edges per thread, int2 loads) ----
__global__ void k_fill(const int* __restrict__ ei, int E, int n) {
    int p = blockIdx.x * blockDim.x + threadIdx.x;
    int e = p * 2;
    if (e + 1 < E) {
        int2 sv = *(const int2*)(ei + e);
        int2 dv = *(const int2*)(ei + E + e);
        if ((unsigned)sv.x < (unsigned)n && (unsigned)dv.x < (unsigned)n) {
            int pos = atomicAdd(&g_cursor[dv.x], 1);
            g_csrc[pos] = sv.x;
        }
        if ((unsigned)sv.y < (unsigned)n && (unsigned)dv.y < (unsigned)n) {
            int pos = atomicAdd(&g_cursor[dv.y], 1);
            g_csrc[pos] = sv.y;
        }
    } else if (e < E) {
        int sv = ei[e], dv = ei[E + e];
        if ((unsigned)sv < (unsigned)n && (unsigned)dv < (unsigned)n) {
            int pos = atomicAdd(&g_cursor[dv], 1);
            g_csrc[pos] = sv;
        }
    }
}

// ---- GEMM1: T = X @ W1 (raw; fp16 out; concurrent with CSR build) ----
__global__ void k_gemm1(const float* __restrict__ X, const float* __restrict__ W,
                        int n) {
    const int K = 128;
    extern __shared__ __align__(16) float sm[];
    float* Wt = sm;                       // [64][132]
    float* Xs = sm + HD * (K + 4);        // [64][132]
    const int NF4 = K / 4;

    int tid = threadIdx.x;
    int row0 = blockIdx.x * 64;

    for (int idx = tid; idx < K * HD; idx += 256) {
        int k = idx >> 6, c = idx & 63;
        Wt[c * (K + 4) + k] = W[idx];
    }
    for (int i = tid; i < 64 * NF4; i += 256) {
        int r = i / NF4, c = i % NF4;
        int rr = row0 + r;
        float4 v = make_float4(0.f, 0.f, 0.f, 0.f);
        if (rr < n) v = ((const float4*)X)[(size_t)rr * NF4 + c];
        *(float4*)&Xs[r * (K + 4) + c * 4] = v;
    }
    __syncthreads();

    int warp = tid >> 5, lane = tid & 31;
    const float* wt0 = &Wt[lane * (K + 4)];
    const float* wt1 = &Wt[(lane + 32) * (K + 4)];
    const float* xr0 = &Xs[(warp * 8) * (K + 4)];

    u64 acc0[8], acc1[8];
#pragma unroll
    for (int r = 0; r < 8; r++) { acc0[r] = 0ull; acc1[r] = 0ull; }

#pragma unroll 4
    for (int k = 0; k < K; k += 4) {
        float4 wa = *(const float4*)(wt0 + k);
        float4 wb = *(const float4*)(wt1 + k);
        u64 wa01 = pk2(wa.x, wa.y), wa23 = pk2(wa.z, wa.w);
        u64 wb01 = pk2(wb.x, wb.y), wb23 = pk2(wb.z, wb.w);
#pragma unroll
        for (int r = 0; r < 8; r++) {
            float4 xv = *(const float4*)(xr0 + r * (K + 4) + k);
            u64 x01 = pk2(xv.x, xv.y), x23 = pk2(xv.z, xv.w);
            fma2(acc0[r], x01, wa01); fma2(acc0[r], x23, wa23);
            fma2(acc1[r], x01, wb01); fma2(acc1[r], x23, wb23);
        }
    }

    int rbase = row0 + warp * 8;
#pragma unroll
    for (int r = 0; r < 8; r++) {
        int rr = rbase + r;
        float a0 = hsum2(acc0[r]);                 // col lane
        float a1 = hsum2(acc1[r]);                 // col lane+32
        float n0 = __shfl_down_sync(0xffffffffu, a0, 1);   // col lane+1
        float n1 = __shfl_down_sync(0xffffffffu, a1, 1);   // col lane+33
        if (((lane & 1) == 0) && rr < n) {
            __half2* row = g_T + (size_t)rr * 32;
            row[(lane >> 1)]      = __floats2half2_rn(a0, n0);
            row[16 + (lane >> 1)] = __floats2half2_rn(a1, n1);
        }
    }
}

// ---- fused gather1 + GEMM2 (agg1 in fp32 smem); fp16 table loads ----
__global__ void k_fuse1(const float* __restrict__ W2, const float* __restrict__ b1,
                        int n) {
    const int K = 64;
    extern __shared__ __align__(16) float sm[];
    float* Wt = sm;                       // [64][68]
    float* Xs = sm + HD * (K + 4);        // [64][68]

    int tid = threadIdx.x;
    int row0 = blockIdx.x * 64;

    for (int idx = tid; idx < K * HD; idx += 256) {
        int k = idx >> 6, c = idx & 63;
        Wt[c * (K + 4) + k] = W2[idx];
    }

    // gather phase: 16 lanes/node, 16 nodes in flight, 4 passes
    int l = tid & 15;
    float4 bb = ((const float4*)b1)[l];
#pragma unroll
    for (int it = 0; it < 4; it++) {
        int r = it * 16 + (tid >> 4);
        int v = row0 + r;
        float4 s = make_float4(0.f, 0.f, 0.f, 0.f);
        if (v < n) {
            float dv = g_dinv[v];
            float4 t = ldh4(g_T + (size_t)v * 32, l);
            s.x = t.x * dv; s.y = t.y * dv; s.z = t.z * dv; s.w = t.w * dv;
            int start = g_rowptr[v];
            int cnt   = g_cnt[v];
            int u = (cnt > 0) ? g_csrc[start] : 0;
            for (int j = 0; j < cnt; j++) {
                int un = (j + 1 < cnt) ? g_csrc[start + j + 1] : 0;
                float du = g_dinv[u];
                float4 tu = ldh4(g_T + (size_t)u * 32, l);
                s.x += tu.x * du; s.y += tu.y * du;
                s.z += tu.z * du; s.w += tu.w * du;
                u = un;
            }
            s.x = fmaxf(dv * s.x + bb.x, 0.0f);
            s.y = fmaxf(dv * s.y + bb.y, 0.0f);
            s.z = fmaxf(dv * s.z + bb.z, 0.0f);
            s.w = fmaxf(dv * s.w + bb.w, 0.0f);
        }
        *(float4*)&Xs[r * (K + 4) + l * 4] = s;
    }
    __syncthreads();

    // GEMM phase (packed f32x2)
    int warp = tid >> 5, lane = tid & 31;
    const float* wt0 = &Wt[lane * (K + 4)];
    const float* wt1 = &Wt[(lane + 32) * (K + 4)];
    const float* xr0 = &Xs[(warp * 8) * (K + 4)];

    u64 acc0[8], acc1[8];
#pragma unroll
    for (int r = 0; r < 8; r++) { acc0[r] = 0ull; acc1[r] = 0ull; }

#pragma unroll 4
    for (int k = 0; k < K; k += 4) {
        float4 wa = *(const float4*)(wt0 + k);
        float4 wb = *(const float4*)(wt1 + k);
        u64 wa01 = pk2(wa.x, wa.y), wa23 = pk2(wa.z, wa.w);
        u64 wb01 = pk2(wb.x, wb.y), wb23 = pk2(wb.z, wb.w);
#pragma unroll
        for (int r = 0; r < 8; r++) {
            float4 xv = *(const float4*)(xr0 + r * (K + 4) + k);
            u64 x01 = pk2(xv.x, xv.y), x23 = pk2(xv.z, xv.w);
            fma2(acc0[r], x01, wa01); fma2(acc0[r], x23, wa23);
            fma2(acc1[r], x01, wb01); fma2(acc1[r], x23, wb23);
        }
    }

    int rbase = row0 + warp * 8;
#pragma unroll
    for (int r = 0; r < 8; r++) {
        int rr = rbase + r;
        float di = (rr < n) ? g_dinv[rr] : 0.0f;
        float a0 = hsum2(acc0[r]) * di;            // col lane (premult dinv)
        float a1 = hsum2(acc1[r]) * di;            // col lane+32
        float n0 = __shfl_down_sync(0xffffffffu, a0, 1);
        float n1 = __shfl_down_sync(0xffffffffu, a1, 1);
        if (((lane & 1) == 0) && rr < n) {
            __half2* row = g_T2 + (size_t)rr * 32;
            row[(lane >> 1)]      = __floats2half2_rn(a0, n0);
            row[16 + (lane >> 1)] = __floats2half2_rn(a1, n1);
        }
    }
}

// ---- fused gather2 + heads; self-cleans g_cnt for the next replay ----
__global__ void k_fuse2(const float* __restrict__ b2, const int* __restrict__ batch,
                        const float* __restrict__ Wa, const float* __restrict__ ba,
                        float* __restrict__ out, int n) {
    int tid = blockIdx.x * blockDim.x + threadIdx.x;
    int v = tid >> 4;
    if (v >= n) return;
    int l = tid & 15;
    int start = g_rowptr[v];
    int cnt   = g_cnt[v];
    if (l == 0) g_cnt[v] = 0;                      // restore zeroed invariant
    float4 s = ldh4(g_T2 + (size_t)v * 32, l);     // self (premult dinv)
    int u = (cnt > 0) ? g_csrc[start] : 0;
    for (int j = 0; j < cnt; j++) {
        int un = (j + 1 < cnt) ? g_csrc[start + j + 1] : 0;
        float4 t = ldh4(g_T2 + (size_t)u * 32, l);
        s.x += t.x; s.y += t.y; s.z += t.z; s.w += t.w;
        u = un;
    }
    float dv = g_dinv[v];
    float4 bb = ((const float4*)b2)[l];
    float4 h;
    h.x = fmaxf(bb.x + dv * s.x, 0.0f);
    h.y = fmaxf(bb.y + dv * s.y, 0.0f);
    h.z = fmaxf(bb.z + dv * s.z, 0.0f);
    h.w = fmaxf(bb.w + dv * s.w, 0.0f);

    float4 wa = ((const float4*)Wa)[l];
    float sl = h.x * wa.x + h.y * wa.y + h.z * wa.z + h.w * wa.w;
    sl += __shfl_xor_sync(0xffffffffu, sl, 8);
    sl += __shfl_xor_sync(0xffffffffu, sl, 4);
    sl += __shfl_xor_sync(0xffffffffu, sl, 2);
    sl += __shfl_xor_sync(0xffffffffu, sl, 1);

    int g = batch[v];
    if ((unsigned)g < (unsigned)MAXG) {
        atomic_add_v4((float4*)(g_pooled + g * HD) + l, h);
        if (l == 0) atomicAdd(&g_counts[g], 1.0f);
    }
    if (l == 0) out[v] = sl + ba[0];
}

// ---- value head; self-cleans g_pooled/g_counts for the next replay ----
__global__ void k_value(const float* __restrict__ Wc, const float* __restrict__ bc,
                        float* __restrict__ out, int n) {
    int g = blockIdx.x, lane = threadIdx.x;
    float p0 = g_pooled[g * HD + lane];
    float p1 = g_pooled[g * HD + 32 + lane];
    float s = p0 * Wc[lane] + p1 * Wc[32 + lane];
    s += __shfl_xor_sync(0xffffffffu, s, 16);
    s += __shfl_xor_sync(0xffffffffu, s, 8);
    s += __shfl_xor_sync(0xffffffffu, s, 4);
    s += __shfl_xor_sync(0xffffffffu, s, 2);
    s += __shfl_xor_sync(0xffffffffu, s, 1);
    if (lane == 0)
        out[n + g] = s / fmaxf(g_counts[g], 1.0f) + bc[0];
    g_pooled[g * HD + lane]      = 0.0f;           // restore zeroed invariant
    g_pooled[g * HD + 32 + lane] = 0.0f;
    if (lane == 0) g_counts[g] = 0.0f;
}

extern "C" void kernel_launch(void* const* d_in, const int* in_sizes, int n_in,
                              void* d_out, int out_size) {
    const float* x     = (const float*)d_in[0];
    const int*   ei    = (const int*)d_in[1];      // int32 (JAX x64 disabled)
    const int*   batch = (const int*)d_in[2];      // int32
    const float* W1    = (const float*)d_in[3];
    const float* b1    = (const float*)d_in[4];
    const float* W2    = (const float*)d_in[5];
    const float* b2    = (const float*)d_in[6];
    const float* Wa    = (const float*)d_in[7];
    const float* ba    = (const float*)d_in[8];
    const float* Wc    = (const float*)d_in[9];
    const float* bc    = (const float*)d_in[10];
    float* out = (float*)d_out;

    int n = in_sizes[2];
    int E = in_sizes[1] / 2;
    int G = out_size - n;   // = 64
    int nb = (n + SCB - 1) / SCB;
    int ne2 = (E + 1) / 2;  // edge-pair count

    int smem1 = 2 * HD * (128 + 4) * sizeof(float);   // 67584 (GEMM1)
    int smemF = 2 * HD * (64 + 4) * sizeof(float);    // 34816 (fuse1)
    cudaFuncSetAttribute(k_gemm1, cudaFuncAttributeMaxDynamicSharedMemorySize, smem1);
    cudaFuncSetAttribute(k_fuse1, cudaFuncAttributeMaxDynamicSharedMemorySize, smemF);

    // ---- fork: GEMM1 on side stream, CSR build on main stream ----
    cudaStream_t s1;
    cudaStreamCreateWithFlags(&s1, cudaStreamNonBlocking);
    cudaEvent_t ev_fork, ev_join;
    cudaEventCreateWithFlags(&ev_fork, cudaEventDisableTiming);
    cudaEventCreateWithFlags(&ev_join, cudaEventDisableTiming);

    cudaEventRecord(ev_fork, 0);
    cudaStreamWaitEvent(s1, ev_fork, 0);
    k_gemm1<<<(n + 63) / 64, 256, smem1, s1>>>(x, W1, n);
    cudaEventRecord(ev_join, s1);

    // CSR build (g_cnt arrives zeroed from the previous replay / module load)
    k_hist<<<(ne2 + 255) / 256, 256>>>(ei, E, n);
    k_scan1<<<nb, SCB>>>(n);
    k_scanB<<<(n + 255) / 256, 256>>>(n, nb);
    k_fill<<<(ne2 + 255) / 256, 256>>>(ei, E, n);

    cudaStreamWaitEvent(0, ev_join, 0);   // join GEMM1

    k_fuse1<<<(n + 63) / 64, 256, smemF>>>(W2, b1, n);
    k_fuse2<<<(n * 16 + 255) / 256, 256>>>(b2, batch, Wa, ba, out, n);
    if (G > 0) k_value<<<G, 32>>>(Wc, bc, out, n);

    cudaEventDestroy(ev_fork);
    cudaEventDestroy(ev_join);
    cudaStreamDestroy(s1);
}